// round 6
// baseline (speedup 1.0000x reference)
#include <cuda_runtime.h>

#define VOX 262144   // 16 * 128 * 128
#define EPSV 1e-5f

// ---------------- scratch (device globals; no allocation allowed) ----------
__device__ int   g_count;
__device__ int   g_map[VOX];
__device__ int   g_list[VOX];
__device__ float g_xa[VOX * 64];      // compact input  [slot][64]
__device__ float g_s1[VOX * 64];      // branch1 intermediate
__device__ float g_r1[VOX * 64];      // branch2 intermediate
__device__ float g_sc[VOX * 128];     // shortcut       [slot][128]
__device__ float g_Wt1a[9 * 64 * 64];
__device__ float g_Wt1b[9 * 64 * 128];
__device__ float g_Wt2a[9 * 64 * 64];
__device__ float g_Wt2b[9 * 64 * 128];

// ---------------- packed fp32 helpers (sm_103a f32x2) ----------------------
__device__ __forceinline__ void ffma2(unsigned long long& d,
                                      unsigned long long a,
                                      unsigned long long b) {
    asm("fma.rn.f32x2 %0, %1, %2, %0;" : "+l"(d) : "l"(a), "l"(b));
}
__device__ __forceinline__ unsigned long long pack2(float x) {
    unsigned long long r;
    asm("mov.b64 %0, {%1, %1};" : "=l"(r) : "f"(x));
    return r;
}

// ---------------- prep: reset counter + transpose all 4 weights -------------
// W is OIDHW flattened: idx = (o*64 + i)*9 + t  ->  Wt[(t*64 + i)*CO + o]
__device__ __forceinline__ void tr_one(const float* __restrict__ W,
                                       float* __restrict__ Wt, int CO, int idx) {
    int t  = idx % 9;
    int oi = idx / 9;
    int i  = oi & 63;
    int o  = oi / 64;
    Wt[(t * 64 + i) * CO + o] = W[idx];
}

__global__ void __launch_bounds__(256) prep(
    const float* __restrict__ W1a, const float* __restrict__ W1b,
    const float* __restrict__ W2a, const float* __restrict__ W2b)
{
    int idx = blockIdx.x * 256 + threadIdx.x;
    if (idx == 0) g_count = 0;
    const int N64 = 64 * 64 * 9, N128 = 128 * 64 * 9;
    if (idx < N64)                      tr_one(W1a, g_Wt1a, 64,  idx);
    else if ((idx -= N64)  < N128)      tr_one(W1b, g_Wt1b, 128, idx);
    else if ((idx -= N128) < N64)       tr_one(W2a, g_Wt2a, 64,  idx);
    else if ((idx -= N64)  < N128)      tr_one(W2b, g_Wt2b, 128, idx);
}

// ---------------- pass 0: activity detection + compaction ------------------
__global__ void __launch_bounds__(256) pass0(const float* __restrict__ x) {
    int v = blockIdx.x * 256 + threadIdx.x;
    float vals[64];
    bool active = false;
#pragma unroll
    for (int c = 0; c < 64; c++) {
        vals[c] = x[c * VOX + v];
        active |= (vals[c] != 0.0f);
    }
    unsigned m   = __ballot_sync(0xffffffffu, active);
    int lane     = threadIdx.x & 31;
    int slot     = -1;
    if (m) {
        int leader = __ffs(m) - 1;
        int base   = 0;
        if (lane == leader) base = atomicAdd(&g_count, __popc(m));
        base = __shfl_sync(0xffffffffu, base, leader);
        if (active) slot = base + __popc(m & ((1u << lane) - 1u));
    }
    g_map[v] = slot;
    if (active) {
        g_list[slot] = v;
#pragma unroll
        for (int c = 0; c < 64; c += 4)
            *(float4*)&g_xa[slot * 64 + c] =
                make_float4(vals[c], vals[c + 1], vals[c + 2], vals[c + 3]);
    }
}

// ---------------- gather-GEMM conv + fused GroupNorm (+LeakyReLU) ----------
// ctype 0: taps (dd,dh,0);  1: (0,dh,dw);  2: (dd,0,dw)   [runtime, used 9x]
// Block: 64 voxels x COUT outputs, 256 threads. f32x2 packed, fat tiles.
// DUAL: grid doubled; upper half runs ctype2 -> out2 (merged conv1+conv3).
template <int COUT, bool LRELU, bool FINAL, bool DUAL>
__global__ void __launch_bounds__(256) conv_gn(
    const float* __restrict__ in, const float* __restrict__ Wt,
    const float* __restrict__ gamma, const float* __restrict__ beta,
    float* __restrict__ outc, float* __restrict__ out2,
    const float* __restrict__ shortcut, float* __restrict__ outd,
    int ctype0, int nb)
{
    const int N   = g_count;
    int bid       = blockIdx.x;
    int ctype     = ctype0;
    float* outp   = outc;
    if (DUAL && bid >= nb) { bid -= nb; ctype = 2; outp = out2; }
    const int base = bid * 64;
    if (base >= N) return;

    constexpr int CW = 8;                // couts per thread (4 f32x2 pairs)
    constexpr int TX = COUT / CW;        // threads along cout: 16 (128) / 8 (64)
    constexpr int VT = TX / 4;           // voxels per thread:   4 (128) / 2 (64)

    extern __shared__ float sbuf[];
    float* Xs = sbuf;                    // [64][68]
    float* Ws = sbuf + 64 * 68;          // [64][COUT]
    __shared__ int nsrow[64];

    const int t  = threadIdx.x;
    const int tx = t % TX;
    const int ty = t / TX;

    unsigned long long acc[VT][4];
#pragma unroll
    for (int j = 0; j < VT; j++)
#pragma unroll
        for (int p = 0; p < 4; p++) acc[j][p] = 0ull;

    for (int tap = 0; tap < 9; tap++) {
        // stage this tap's 64xCOUT weight tile
        const float4* wsrc = (const float4*)(Wt + tap * 64 * COUT);
#pragma unroll
        for (int k = t; k < 16 * COUT; k += 256)
            ((float4*)Ws)[k] = wsrc[k];

        // neighbor slot per row
        if (t < 64) {
            int slot = base + t, ns = -1;
            if (slot < N) {
                int v = g_list[slot];
                int d = v >> 14, h = (v >> 7) & 127, w = v & 127;
                int da = tap / 3 - 1, db = tap % 3 - 1;
                int dd = (ctype != 1) ? da : 0;
                int dh = (ctype == 0) ? db : ((ctype == 1) ? da : 0);
                int dw = (ctype == 0) ? 0  : db;
                d += dd; h += dh; w += dw;
                if ((unsigned)d < 16u && (unsigned)h < 128u && (unsigned)w < 128u)
                    ns = g_map[(d << 14) | (h << 7) | w];
            }
            nsrow[t] = ns;
        }
        __syncthreads();

        // gather 64 input rows (256B each, contiguous) into Xs
        {
            int r = t >> 2, p = t & 3;
            int ns = nsrow[r];
            const float4* src = (const float4*)(in + ns * 64 + p * 16);
#pragma unroll
            for (int k = 0; k < 4; k++) {
                float4 val = (ns >= 0) ? src[k] : make_float4(0.f, 0.f, 0.f, 0.f);
                *(float4*)&Xs[r * 68 + p * 16 + k * 4] = val;
            }
        }
        __syncthreads();

        // fat microkernel: VT voxels x CW couts per thread, f32x2 packed
#pragma unroll 2
        for (int i0 = 0; i0 < 64; i0 += 4) {
            float4 a4[VT];
#pragma unroll
            for (int j = 0; j < VT; j++)
                a4[j] = *(const float4*)&Xs[(ty * VT + j) * 68 + i0];
#pragma unroll
            for (int ii = 0; ii < 4; ii++) {
                const float* wrow = &Ws[(i0 + ii) * COUT + tx * CW];
                ulonglong2 b0 = *(const ulonglong2*)(wrow);
                ulonglong2 b1 = *(const ulonglong2*)(wrow + 4);
#pragma unroll
                for (int j = 0; j < VT; j++) {
                    float a = (ii == 0) ? a4[j].x : (ii == 1) ? a4[j].y
                            : (ii == 2) ? a4[j].z : a4[j].w;
                    unsigned long long aa = pack2(a);
                    ffma2(acc[j][0], aa, b0.x);
                    ffma2(acc[j][1], aa, b0.y);
                    ffma2(acc[j][2], aa, b1.x);
                    ffma2(acc[j][3], aa, b1.y);
                }
            }
        }
        __syncthreads();
    }

    // spill conv results to smem for the GroupNorm remap
    float* S = sbuf;  // [64][COUT], reuses Xs+Ws region
#pragma unroll
    for (int j = 0; j < VT; j++) {
        float* dst = &S[(ty * VT + j) * COUT + tx * CW];
        float2 p0 = *(float2*)&acc[j][0];
        float2 p1 = *(float2*)&acc[j][1];
        float2 p2 = *(float2*)&acc[j][2];
        float2 p3 = *(float2*)&acc[j][3];
        *(float4*)(dst)     = make_float4(p0.x, p0.y, p1.x, p1.y);
        *(float4*)(dst + 4) = make_float4(p2.x, p2.y, p3.x, p3.y);
    }
    __syncthreads();

    // GroupNorm: 32 groups of CG consecutive channels, per-voxel stats
    constexpr int CG = COUT / 32;
    for (int task = t; task < 64 * 32; task += 256) {
        int vox  = task >> 5;
        int g    = task & 31;
        int slot = base + vox;
        if (slot >= N) continue;
        float vals[CG], sum = 0.f;
#pragma unroll
        for (int c = 0; c < CG; c++) { vals[c] = S[vox * COUT + g * CG + c]; sum += vals[c]; }
        float mu  = sum * (1.0f / CG);
        float var = 0.f;
#pragma unroll
        for (int c = 0; c < CG; c++) { float d = vals[c] - mu; var += d * d; }
        var *= (1.0f / CG);
        float rs = rsqrtf(var + EPSV);
        if (!FINAL) {
#pragma unroll
            for (int c = 0; c < CG; c++) {
                int cc  = g * CG + c;
                float o = (vals[c] - mu) * rs * gamma[cc] + beta[cc];
                if (LRELU) o = (o > 0.f) ? o : 0.01f * o;
                outp[slot * COUT + cc] = o;
            }
        } else {
            int v = g_list[slot];
#pragma unroll
            for (int c = 0; c < CG; c++) {
                int cc  = g * CG + c;
                float o = (vals[c] - mu) * rs * gamma[cc] + beta[cc]
                        + shortcut[slot * 128 + cc];
                outd[cc * VOX + v] = o;
            }
        }
    }
}

// ---------------- launch ----------------------------------------------------
extern "C" void kernel_launch(void* const* d_in, const int* in_sizes, int n_in,
                              void* d_out, int out_size) {
    (void)in_sizes; (void)n_in; (void)out_size;
    const float* x   = (const float*)d_in[0];
    // d_in[1] = mask (dtype uncertain) — activity derived from x instead.
    const float* W1a = (const float*)d_in[2];
    const float* g1a = (const float*)d_in[3];
    const float* b1a = (const float*)d_in[4];
    const float* W1b = (const float*)d_in[5];
    const float* g1b = (const float*)d_in[6];
    const float* b1b = (const float*)d_in[7];
    const float* W2a = (const float*)d_in[8];
    const float* g2a = (const float*)d_in[9];
    const float* b2a = (const float*)d_in[10];
    const float* W2b = (const float*)d_in[11];
    const float* g2b = (const float*)d_in[12];
    const float* b2b = (const float*)d_in[13];
    float* out = (float*)d_out;

    float *p_xa, *p_s1, *p_r1, *p_sc, *p_w1a, *p_w1b, *p_w2a, *p_w2b;
    cudaGetSymbolAddress((void**)&p_xa,  g_xa);
    cudaGetSymbolAddress((void**)&p_s1,  g_s1);
    cudaGetSymbolAddress((void**)&p_r1,  g_r1);
    cudaGetSymbolAddress((void**)&p_sc,  g_sc);
    cudaGetSymbolAddress((void**)&p_w1a, g_Wt1a);
    cudaGetSymbolAddress((void**)&p_w1b, g_Wt1b);
    cudaGetSymbolAddress((void**)&p_w2a, g_Wt2a);
    cudaGetSymbolAddress((void**)&p_w2b, g_Wt2b);

    const int SM64  = (64 * 68 + 64 * 64) * 4;   // 33792 B
    const int SM128 = (64 * 68 + 64 * 128) * 4;  // 50176 B
    cudaFuncSetAttribute(conv_gn<128, false, false, false>,
                         cudaFuncAttributeMaxDynamicSharedMemorySize, SM128);
    cudaFuncSetAttribute(conv_gn<128, false, true, false>,
                         cudaFuncAttributeMaxDynamicSharedMemorySize, SM128);

    cudaMemsetAsync(out, 0, (size_t)VOX * 128 * sizeof(float), 0);

    const int NPREP = 2 * (64 * 64 * 9) + 2 * (128 * 64 * 9);
    prep<<<(NPREP + 255) / 256, 256>>>(W1a, W1b, W2a, W2b);
    pass0<<<VOX / 256, 256>>>(x);

    const int NB = VOX / 64;  // worst-case all-active; blocks early-exit past g_count

    // merged conv1 (ctype0 -> s1) + conv3 (ctype2 -> r1), both from xa
    // NOTE: both read the same weights? No — conv1 uses W1a, conv3 uses W2a.
    // They share the DUAL kernel but need separate Wt pointers; Wt1a/Wt2a are
    // contiguous in distinct arrays, so pass Wt per half via the ctype branch:
    // here we exploit that g_Wt2a immediately follows? Not guaranteed — instead
    // launch DUAL with Wt selected inside via pointer arithmetic is unsafe.
    // So: keep conv1/conv3 as two launches of the same template (cheap), DUAL unused for Wt reasons.
    conv_gn<64, true, false, false><<<NB, 256, SM64>>>(
        p_xa, p_w1a, g1a, b1a, p_s1, nullptr, nullptr, nullptr, 0, NB);
    conv_gn<64, true, false, false><<<NB, 256, SM64>>>(
        p_xa, p_w2a, g2a, b2a, p_r1, nullptr, nullptr, nullptr, 2, NB);
    conv_gn<128, false, false, false><<<NB, 256, SM128>>>(
        p_s1, p_w1b, g1b, b1b, p_sc, nullptr, nullptr, nullptr, 1, NB);
    conv_gn<128, false, true, false><<<NB, 256, SM128>>>(
        p_r1, p_w2b, g2b, b2b, nullptr, nullptr, p_sc, out, 0, NB);
}

// round 9
// speedup vs baseline: 1.5135x; 1.5135x over previous
#include <cuda_runtime.h>
#include <cstdint>

#define VOX 262144   // 16 * 128 * 128
#define EPSV 1e-5f

// ---------------- scratch (device globals; no allocation allowed) ----------
__device__ int   g_count;
__device__ int   g_map[VOX];
__device__ int   g_list[VOX];
__device__ float g_xa[VOX * 64];      // compact input  [slot][64]
__device__ float g_s1[VOX * 64];      // branch1 intermediate
__device__ float g_r1[VOX * 64];      // branch2 intermediate
__device__ float g_sc[VOX * 128];     // shortcut       [slot][128]
__device__ float g_Wt1a[9 * 64 * 64];
__device__ float g_Wt1b[9 * 64 * 128];
__device__ float g_Wt2a[9 * 64 * 64];
__device__ float g_Wt2b[9 * 64 * 128];

// ---------------- packed fp32 helpers (sm_103a f32x2) ----------------------
__device__ __forceinline__ void ffma2(unsigned long long& d,
                                      unsigned long long a,
                                      unsigned long long b) {
    asm("fma.rn.f32x2 %0, %1, %2, %0;" : "+l"(d) : "l"(a), "l"(b));
}
__device__ __forceinline__ unsigned long long pack2(float x) {
    unsigned long long r;
    asm("mov.b64 %0, {%1, %1};" : "=l"(r) : "f"(x));
    return r;
}

// ---------------- cp.async helpers -----------------------------------------
__device__ __forceinline__ uint32_t sptr(const void* p) {
    return (uint32_t)__cvta_generic_to_shared(p);
}
__device__ __forceinline__ void cp_async16(uint32_t dst, const void* src, int srcsize) {
    asm volatile("cp.async.ca.shared.global [%0], [%1], 16, %2;"
                 :: "r"(dst), "l"(src), "r"(srcsize));
}
__device__ __forceinline__ void cp_commit() {
    asm volatile("cp.async.commit_group;");
}
template <int NN>
__device__ __forceinline__ void cp_wait() {
    asm volatile("cp.async.wait_group %0;" :: "n"(NN));
}

// ---------------- prep: reset counter + transpose all 4 weights -------------
// W is OIDHW flattened: idx = (o*64 + i)*9 + t  ->  Wt[(t*64 + i)*CO + o]
__device__ __forceinline__ void tr_one(const float* __restrict__ W,
                                       float* __restrict__ Wt, int CO, int idx) {
    int t  = idx % 9;
    int oi = idx / 9;
    int i  = oi & 63;
    int o  = oi / 64;
    Wt[(t * 64 + i) * CO + o] = W[idx];
}

__global__ void __launch_bounds__(256) prep(
    const float* __restrict__ W1a, const float* __restrict__ W1b,
    const float* __restrict__ W2a, const float* __restrict__ W2b)
{
    int idx = blockIdx.x * 256 + threadIdx.x;
    if (idx == 0) g_count = 0;
    const int N64 = 64 * 64 * 9, N128 = 128 * 64 * 9;
    if (idx < N64)                      tr_one(W1a, g_Wt1a, 64,  idx);
    else if ((idx -= N64)  < N128)      tr_one(W1b, g_Wt1b, 128, idx);
    else if ((idx -= N128) < N64)       tr_one(W2a, g_Wt2a, 64,  idx);
    else if ((idx -= N64)  < N128)      tr_one(W2b, g_Wt2b, 128, idx);
}

// ---------------- pass 0: activity detection + compaction ------------------
__global__ void __launch_bounds__(256) pass0(const float* __restrict__ x) {
    int v = blockIdx.x * 256 + threadIdx.x;
    float vals[64];
    bool active = false;
#pragma unroll
    for (int c = 0; c < 64; c++) {
        vals[c] = x[c * VOX + v];
        active |= (vals[c] != 0.0f);
    }
    unsigned m   = __ballot_sync(0xffffffffu, active);
    int lane     = threadIdx.x & 31;
    int slot     = -1;
    if (m) {
        int leader = __ffs(m) - 1;
        int base   = 0;
        if (lane == leader) base = atomicAdd(&g_count, __popc(m));
        base = __shfl_sync(0xffffffffu, base, leader);
        if (active) slot = base + __popc(m & ((1u << lane) - 1u));
    }
    g_map[v] = slot;
    if (active) {
        g_list[slot] = v;
#pragma unroll
        for (int c = 0; c < 64; c += 4)
            *(float4*)&g_xa[slot * 64 + c] =
                make_float4(vals[c], vals[c + 1], vals[c + 2], vals[c + 3]);
    }
}

// ---------------- gather-GEMM conv + fused GroupNorm (+LeakyReLU) ----------
// CTYPE 0: (3,3,1) taps -> (dd,dh,0);  1: (1,3,3) -> (0,dh,dw);  2: (3,1,3) -> (dd,0,dw)
// Block: 64 voxels x COUT outputs, 256 threads.
// Round-4 conflict-free microkernel (CW=4) + cp.async double-buffered pipeline.
template <int COUT, int CTYPE, bool LRELU, bool FINAL>
__global__ void __launch_bounds__(256) conv_gn(
    const float* __restrict__ in, const float* __restrict__ Wt,
    const float* __restrict__ gamma, const float* __restrict__ beta,
    float* __restrict__ outc, const float* __restrict__ shortcut,
    float* __restrict__ outd)
{
    const int N    = g_count;
    const int base = blockIdx.x * 64;
    if (base >= N) return;

    constexpr int TX  = COUT / 4;        // threads along out-channels (x4 each)
    constexpr int VT  = 64 * TX / 256;   // voxels per thread (8 for 128, 4 for 64)
    constexpr int XSF = 64 * 68;         // floats per Xs buffer
    constexpr int WSF = 64 * COUT;       // floats per Ws buffer

    extern __shared__ float sbuf[];
    float* Xb[2] = { sbuf,            sbuf + XSF };
    float* Wb[2] = { sbuf + 2 * XSF,  sbuf + 2 * XSF + WSF };
    __shared__ int nsrow[9][64];

    const int t  = threadIdx.x;
    const int tx = t % TX;
    const int ty = t / TX;

    // ---- neighbor slots for all 9 taps, once ----
    for (int task = t; task < 9 * 64; task += 256) {
        int tap  = task >> 6;
        int r    = task & 63;
        int slot = base + r, ns = -1;
        if (slot < N) {
            int v = g_list[slot];
            int d = v >> 14, h = (v >> 7) & 127, w = v & 127;
            int dd, dh, dw;
            if (CTYPE == 0)      { dd = tap / 3 - 1; dh = tap % 3 - 1; dw = 0; }
            else if (CTYPE == 1) { dd = 0;           dh = tap / 3 - 1; dw = tap % 3 - 1; }
            else                 { dd = tap / 3 - 1; dh = 0;           dw = tap % 3 - 1; }
            d += dd; h += dh; w += dw;
            if ((unsigned)d < 16u && (unsigned)h < 128u && (unsigned)w < 128u)
                ns = g_map[(d << 14) | (h << 7) | w];
        }
        nsrow[tap][r] = ns;
    }
    __syncthreads();

    // ---- async stage of one tap into buffer buf ----
    const int gr = t >> 2, gp = t & 3;   // gather: 4 threads per row
    auto stage = [&](int tap, int buf) {
        const float4* wsrc = (const float4*)(Wt + tap * 64 * COUT);
        uint32_t wdst = sptr(Wb[buf]);
#pragma unroll
        for (int k = t; k < 16 * COUT; k += 256)
            cp_async16(wdst + k * 16, wsrc + k, 16);
        int ns  = nsrow[tap][gr];
        int nsc = ns < 0 ? 0 : ns;
        int sz  = ns < 0 ? 0 : 16;
        const float4* src = (const float4*)(in + nsc * 64 + gp * 16);
        uint32_t xdst = sptr(&Xb[buf][gr * 68 + gp * 16]);
#pragma unroll
        for (int k = 0; k < 4; k++)
            cp_async16(xdst + k * 16, src + k, sz);
    };

    unsigned long long acc[VT][2];
#pragma unroll
    for (int j = 0; j < VT; j++) { acc[j][0] = 0ull; acc[j][1] = 0ull; }

    stage(0, 0);
    cp_commit();

    for (int tap = 0; tap < 9; tap++) {
        int buf = tap & 1;
        if (tap < 8) { stage(tap + 1, buf ^ 1); cp_commit(); cp_wait<1>(); }
        else         { cp_wait<0>(); }
        __syncthreads();

        const float* Xs = Xb[buf];
        const float* Ws = Wb[buf];
#pragma unroll 2
        for (int i0 = 0; i0 < 64; i0 += 4) {
            float4 a4[VT];
#pragma unroll
            for (int j = 0; j < VT; j++)
                a4[j] = *(const float4*)&Xs[(ty * VT + j) * 68 + i0];
#pragma unroll
            for (int ii = 0; ii < 4; ii++) {
                ulonglong2 b = *(const ulonglong2*)&Ws[(i0 + ii) * COUT + tx * 4];
#pragma unroll
                for (int j = 0; j < VT; j++) {
                    float a = (ii == 0) ? a4[j].x : (ii == 1) ? a4[j].y
                            : (ii == 2) ? a4[j].z : a4[j].w;
                    unsigned long long aa = pack2(a);
                    ffma2(acc[j][0], aa, b.x);
                    ffma2(acc[j][1], aa, b.y);
                }
            }
        }
        __syncthreads();   // all reads of buf done before it is restaged
    }

    // spill conv results to smem for the GroupNorm remap
    float* S = sbuf;  // [64][COUT], reuses pipeline buffers
#pragma unroll
    for (int j = 0; j < VT; j++) {
        float2 lo = *(float2*)&acc[j][0];
        float2 hi = *(float2*)&acc[j][1];
        *(float4*)&S[(ty * VT + j) * COUT + tx * 4] =
            make_float4(lo.x, lo.y, hi.x, hi.y);
    }
    __syncthreads();

    // GroupNorm: 32 groups of CG consecutive channels, per-voxel stats
    constexpr int CG = COUT / 32;
    for (int task = t; task < 64 * 32; task += 256) {
        int vox  = task >> 5;
        int g    = task & 31;
        int slot = base + vox;
        if (slot >= N) continue;
        float vals[CG], sum = 0.f;
#pragma unroll
        for (int c = 0; c < CG; c++) { vals[c] = S[vox * COUT + g * CG + c]; sum += vals[c]; }
        float mu  = sum * (1.0f / CG);
        float var = 0.f;
#pragma unroll
        for (int c = 0; c < CG; c++) { float d = vals[c] - mu; var += d * d; }
        var *= (1.0f / CG);
        float rs = rsqrtf(var + EPSV);
        if (!FINAL) {
#pragma unroll
            for (int c = 0; c < CG; c++) {
                int cc  = g * CG + c;
                float o = (vals[c] - mu) * rs * gamma[cc] + beta[cc];
                if (LRELU) o = (o > 0.f) ? o : 0.01f * o;
                outc[slot * COUT + cc] = o;
            }
        } else {
            int v = g_list[slot];
#pragma unroll
            for (int c = 0; c < CG; c++) {
                int cc  = g * CG + c;
                float o = (vals[c] - mu) * rs * gamma[cc] + beta[cc]
                        + shortcut[slot * 128 + cc];
                outd[cc * VOX + v] = o;
            }
        }
    }
}

// ---------------- launch ----------------------------------------------------
extern "C" void kernel_launch(void* const* d_in, const int* in_sizes, int n_in,
                              void* d_out, int out_size) {
    (void)in_sizes; (void)n_in; (void)out_size;
    const float* x   = (const float*)d_in[0];
    // d_in[1] = mask (dtype uncertain) — activity derived from x instead.
    const float* W1a = (const float*)d_in[2];
    const float* g1a = (const float*)d_in[3];
    const float* b1a = (const float*)d_in[4];
    const float* W1b = (const float*)d_in[5];
    const float* g1b = (const float*)d_in[6];
    const float* b1b = (const float*)d_in[7];
    const float* W2a = (const float*)d_in[8];
    const float* g2a = (const float*)d_in[9];
    const float* b2a = (const float*)d_in[10];
    const float* W2b = (const float*)d_in[11];
    const float* g2b = (const float*)d_in[12];
    const float* b2b = (const float*)d_in[13];
    float* out = (float*)d_out;

    float *p_xa, *p_s1, *p_r1, *p_sc, *p_w1a, *p_w1b, *p_w2a, *p_w2b;
    cudaGetSymbolAddress((void**)&p_xa,  g_xa);
    cudaGetSymbolAddress((void**)&p_s1,  g_s1);
    cudaGetSymbolAddress((void**)&p_r1,  g_r1);
    cudaGetSymbolAddress((void**)&p_sc,  g_sc);
    cudaGetSymbolAddress((void**)&p_w1a, g_Wt1a);
    cudaGetSymbolAddress((void**)&p_w1b, g_Wt1b);
    cudaGetSymbolAddress((void**)&p_w2a, g_Wt2a);
    cudaGetSymbolAddress((void**)&p_w2b, g_Wt2b);

    // double-buffered smem: 2*(64*68) + 2*(64*COUT) floats
    const int SM64  = (2 * 64 * 68 + 2 * 64 * 64) * 4;   // 67584 B
    const int SM128 = (2 * 64 * 68 + 2 * 64 * 128) * 4;  // 100352 B
    cudaFuncSetAttribute(conv_gn<64, 0, true,  false>,
                         cudaFuncAttributeMaxDynamicSharedMemorySize, SM64);
    cudaFuncSetAttribute(conv_gn<64, 2, true,  false>,
                         cudaFuncAttributeMaxDynamicSharedMemorySize, SM64);
    cudaFuncSetAttribute(conv_gn<128, 1, false, false>,
                         cudaFuncAttributeMaxDynamicSharedMemorySize, SM128);
    cudaFuncSetAttribute(conv_gn<128, 0, false, true>,
                         cudaFuncAttributeMaxDynamicSharedMemorySize, SM128);

    cudaMemsetAsync(out, 0, (size_t)VOX * 128 * sizeof(float), 0);

    const int NPREP = 2 * (64 * 64 * 9) + 2 * (128 * 64 * 9);
    prep<<<(NPREP + 255) / 256, 256>>>(W1a, W1b, W2a, W2b);
    pass0<<<VOX / 256, 256>>>(x);

    const int NB = VOX / 64;  // worst-case all-active; blocks early-exit past g_count
    conv_gn<64, 0, true,  false><<<NB, 256, SM64>>>(p_xa, p_w1a, g1a, b1a, p_s1, nullptr, nullptr);
    conv_gn<64, 2, true,  false><<<NB, 256, SM64>>>(p_xa, p_w2a, g2a, b2a, p_r1, nullptr, nullptr);
    conv_gn<128, 1, false, false><<<NB, 256, SM128>>>(p_s1, p_w1b, g1b, b1b, p_sc, nullptr, nullptr);
    conv_gn<128, 0, false, true><<<NB, 256, SM128>>>(p_r1, p_w2b, g2b, b2b, nullptr, p_sc, out);
}

// round 14
// speedup vs baseline: 2.5950x; 1.7145x over previous
#include <cuda_runtime.h>
#include <cuda_bf16.h>
#include <cstdint>

#define VOX 262144   // 16 * 128 * 128
#define EPSV 1e-5f

// ---------------- scratch (device globals; no allocation allowed) ----------
__device__ int   g_count;
__device__ int   g_map[VOX];
__device__ int   g_list[VOX];
__device__ float g_xa[VOX * 64];      // compact input  [slot][64]
__device__ float g_s1[VOX * 64];      // branch1 intermediate
__device__ float g_r1[VOX * 64];      // branch2 intermediate
__device__ float g_sc[VOX * 128];     // shortcut       [slot][128]
// weights pre-split to bf16 hi/lo, layout [tap][o][i]  (col operand: n-major, k-contig)
__device__ __nv_bfloat16 g_Wh1a[9*64*64],  g_Wl1a[9*64*64];
__device__ __nv_bfloat16 g_Wh1b[9*128*64], g_Wl1b[9*128*64];
__device__ __nv_bfloat16 g_Wh2a[9*64*64],  g_Wl2a[9*64*64];
__device__ __nv_bfloat16 g_Wh2b[9*128*64], g_Wl2b[9*128*64];

// ---------------- PTX helpers ----------------------------------------------
__device__ __forceinline__ uint32_t sptr(const void* p) {
    return (uint32_t)__cvta_generic_to_shared(p);
}
__device__ __forceinline__ void ldsm_x4(uint32_t* r, uint32_t addr) {
    asm volatile("ldmatrix.sync.aligned.m8n8.x4.shared.b16 {%0,%1,%2,%3}, [%4];"
                 : "=r"(r[0]), "=r"(r[1]), "=r"(r[2]), "=r"(r[3]) : "r"(addr));
}
__device__ __forceinline__ void ldsm_x2(uint32_t* r, uint32_t addr) {
    asm volatile("ldmatrix.sync.aligned.m8n8.x2.shared.b16 {%0,%1}, [%2];"
                 : "=r"(r[0]), "=r"(r[1]) : "r"(addr));
}
__device__ __forceinline__ void mma16816(float* d, const uint32_t* a, const uint32_t* b) {
    asm volatile(
        "mma.sync.aligned.m16n8k16.row.col.f32.bf16.bf16.f32 "
        "{%0,%1,%2,%3}, {%4,%5,%6,%7}, {%8,%9}, {%0,%1,%2,%3};"
        : "+f"(d[0]), "+f"(d[1]), "+f"(d[2]), "+f"(d[3])
        : "r"(a[0]), "r"(a[1]), "r"(a[2]), "r"(a[3]), "r"(b[0]), "r"(b[1]));
}

// ---------------- prep: reset counter + split all 4 weights to bf16 hi/lo ---
// W OIDHW flattened: idx = (o*64 + i)*9 + t  ->  Wh/Wl[(t*CO + o)*64 + i]
__device__ __forceinline__ void split_one(const float* __restrict__ W,
                                          __nv_bfloat16* __restrict__ Wh,
                                          __nv_bfloat16* __restrict__ Wl,
                                          int CO, int idx) {
    int t  = idx % 9;
    int oi = idx / 9;
    int i  = oi & 63;
    int o  = oi / 64;
    float w = W[idx];
    __nv_bfloat16 hb = __float2bfloat16(w);
    float rem = w - __bfloat162float(hb);
    __nv_bfloat16 lb = __float2bfloat16(rem);
    Wh[(t * CO + o) * 64 + i] = hb;
    Wl[(t * CO + o) * 64 + i] = lb;
}

__global__ void __launch_bounds__(256) prep(
    const float* __restrict__ W1a, const float* __restrict__ W1b,
    const float* __restrict__ W2a, const float* __restrict__ W2b)
{
    int idx = blockIdx.x * 256 + threadIdx.x;
    if (idx == 0) g_count = 0;
    const int N64 = 64 * 64 * 9, N128 = 128 * 64 * 9;
    if (idx < N64)                 split_one(W1a, g_Wh1a, g_Wl1a, 64,  idx);
    else if ((idx -= N64)  < N128) split_one(W1b, g_Wh1b, g_Wl1b, 128, idx);
    else if ((idx -= N128) < N64)  split_one(W2a, g_Wh2a, g_Wl2a, 64,  idx);
    else if ((idx -= N64)  < N128) split_one(W2b, g_Wh2b, g_Wl2b, 128, idx);
}

// ---------------- pass 0: activity detection + compaction ------------------
__global__ void __launch_bounds__(256) pass0(const float* __restrict__ x) {
    int v = blockIdx.x * 256 + threadIdx.x;
    float vals[64];
    bool active = false;
#pragma unroll
    for (int c = 0; c < 64; c++) {
        vals[c] = x[c * VOX + v];
        active |= (vals[c] != 0.0f);
    }
    unsigned m   = __ballot_sync(0xffffffffu, active);
    int lane     = threadIdx.x & 31;
    int slot     = -1;
    if (m) {
        int leader = __ffs(m) - 1;
        int base   = 0;
        if (lane == leader) base = atomicAdd(&g_count, __popc(m));
        base = __shfl_sync(0xffffffffu, base, leader);
        if (active) slot = base + __popc(m & ((1u << lane) - 1u));
    }
    g_map[v] = slot;
    if (active) {
        g_list[slot] = v;
#pragma unroll
        for (int c = 0; c < 64; c += 4)
            *(float4*)&g_xa[slot * 64 + c] =
                make_float4(vals[c], vals[c + 1], vals[c + 2], vals[c + 3]);
    }
}

// ---------------- warp-MMA gather-GEMM conv + fused GN (+LeakyReLU) --------
// Per block: D[128vox x COUT] = sum_tap X[128x64] @ W_tap[64xCOUT]^T
// bf16 2-way split on HMMA (mma.sync m16n8k16), fp32 register accumulators.
// smem rows padded to 144B (9x16B) -> ldmatrix conflict-free, no swizzle.
// Dynamic smem: Ah[128][72]bf16 @0, Al @18432, Bh[CO][72] @36864, Bl follows.
template <int COUT, int CTYPE, bool LRELU, bool FINAL>
__global__ void __launch_bounds__(256) conv_mma(
    const float* __restrict__ in,
    const __nv_bfloat16* __restrict__ Wh, const __nv_bfloat16* __restrict__ Wl,
    const float* __restrict__ gamma, const float* __restrict__ beta,
    float* __restrict__ outc, const float* __restrict__ shortcut,
    float* __restrict__ outd)
{
    const int N    = g_count;
    const int base = blockIdx.x * 128;
    if (base >= N) return;

    constexpr int NT  = COUT / 8;        // n-tiles per warp
    constexpr int RS  = 144;             // padded smem row stride (bytes)

    extern __shared__ char smem[];
    __shared__ int nsrow[9 * 128];
    char* Ah = smem;
    char* Al = smem + 18432;
    char* Bh = smem + 36864;
    char* Bl = smem + 36864 + COUT * RS;
    const uint32_t aAH = sptr(Ah), aAL = sptr(Al);
    const uint32_t aBH = sptr(Bh), aBL = sptr(Bl);

    const int t    = threadIdx.x;
    const int w    = t >> 5;
    const int lane = t & 31;
    const int eff  = lane & 15;

    // neighbor slots for all 9 taps
    for (int task = t; task < 9 * 128; task += 256) {
        int tap  = task >> 7;
        int r    = task & 127;
        int slot = base + r, ns = -1;
        if (slot < N) {
            int v = g_list[slot];
            int d = v >> 14, h = (v >> 7) & 127, wd = v & 127;
            int dd, dh, dw;
            if (CTYPE == 0)      { dd = tap / 3 - 1; dh = tap % 3 - 1; dw = 0; }
            else if (CTYPE == 1) { dd = 0;           dh = tap / 3 - 1; dw = tap % 3 - 1; }
            else                 { dd = tap / 3 - 1; dh = 0;           dw = tap % 3 - 1; }
            d += dd; h += dh; wd += dw;
            if ((unsigned)d < 16u && (unsigned)h < 128u && (unsigned)wd < 128u)
                ns = g_map[(d << 14) | (h << 7) | wd];
        }
        nsrow[tap * 128 + r] = ns;
    }
    __syncthreads();

    float acc[NT][4];
#pragma unroll
    for (int nt = 0; nt < NT; nt++)
#pragma unroll
        for (int p = 0; p < 4; p++) acc[nt][p] = 0.f;

    // per-thread ldmatrix base addresses
    const uint32_t aoff = (uint32_t)(w * 16 + eff) * RS + ((lane >> 4) & 1) * 16;
    const uint32_t boff0 = (uint32_t)(eff & 7) * RS + ((eff >> 3) & 1) * 16;

    const int gr = t >> 1, gh = t & 1;   // A stage: 2 threads per voxel row

    for (int tap = 0; tap < 9; tap++) {
        // ---- stage A: gather + fp32->bf16 hi/lo split ----
        {
            int ns = nsrow[tap * 128 + gr];
            const float* src = in + (ns < 0 ? 0 : ns) * 64 + gh * 32;
            char* ah = Ah + gr * RS + gh * 64;
            char* al = Al + gr * RS + gh * 64;
#pragma unroll
            for (int j = 0; j < 4; j++) {
                float f[8];
                if (ns >= 0) {
                    float4 a = *(const float4*)(src + j * 8);
                    float4 b = *(const float4*)(src + j * 8 + 4);
                    f[0]=a.x; f[1]=a.y; f[2]=a.z; f[3]=a.w;
                    f[4]=b.x; f[5]=b.y; f[6]=b.z; f[7]=b.w;
                } else {
#pragma unroll
                    for (int e = 0; e < 8; e++) f[e] = 0.f;
                }
                uint32_t hw[4], lw[4];
#pragma unroll
                for (int p = 0; p < 4; p++) {
                    __nv_bfloat16 h0 = __float2bfloat16(f[2*p]);
                    __nv_bfloat16 h1 = __float2bfloat16(f[2*p+1]);
                    float r0 = f[2*p]   - __bfloat162float(h0);
                    float r1 = f[2*p+1] - __bfloat162float(h1);
                    __nv_bfloat16 l0 = __float2bfloat16(r0);
                    __nv_bfloat16 l1 = __float2bfloat16(r1);
                    hw[p] = (uint32_t)__bfloat16_as_ushort(h0)
                          | ((uint32_t)__bfloat16_as_ushort(h1) << 16);
                    lw[p] = (uint32_t)__bfloat16_as_ushort(l0)
                          | ((uint32_t)__bfloat16_as_ushort(l1) << 16);
                }
                *(uint4*)(ah + j * 16) = make_uint4(hw[0], hw[1], hw[2], hw[3]);
                *(uint4*)(al + j * 16) = make_uint4(lw[0], lw[1], lw[2], lw[3]);
            }
        }
        // ---- stage B: copy pre-split weights into padded rows ----
        {
            const uint4* sh = (const uint4*)(Wh + tap * COUT * 64);
            const uint4* sl = (const uint4*)(Wl + tap * COUT * 64);
#pragma unroll
            for (int u = t; u < COUT * 8; u += 256) {
                int row = u >> 3, part = u & 7;
                *(uint4*)(Bh + row * RS + part * 16) = sh[u];
                *(uint4*)(Bl + row * RS + part * 16) = sl[u];
            }
        }
        __syncthreads();

        // ---- warp-MMA mainloop: 4 k-steps x NT n-tiles x 3 split terms ----
#pragma unroll
        for (int ks = 0; ks < 4; ks++) {
            uint32_t ah[4], al[4];
            ldsm_x4(ah, aAH + aoff + ks * 32);
            ldsm_x4(al, aAL + aoff + ks * 32);
#pragma unroll
            for (int nt = 0; nt < NT; nt++) {
                uint32_t bo = boff0 + (uint32_t)(nt * 8) * RS + ks * 32;
                uint32_t bh[2], bl[2];
                ldsm_x2(bh, aBH + bo);
                ldsm_x2(bl, aBL + bo);
                mma16816(acc[nt], ah, bh);
                mma16816(acc[nt], ah, bl);
                mma16816(acc[nt], al, bh);
            }
        }
        __syncthreads();   // all frags consumed before restaging
    }

    // ---- epilogue: D frags -> smem, then GroupNorm (+LReLU / +shortcut) ----
    float* S = (float*)smem;   // [128][COUT], reuses staging buffers
    {
        int r0 = w * 16 + (lane >> 2);
        int c0 = (lane & 3) * 2;
#pragma unroll
        for (int nt = 0; nt < NT; nt++) {
            int cc = nt * 8 + c0;
            *(float2*)&S[r0 * COUT + cc]       = make_float2(acc[nt][0], acc[nt][1]);
            *(float2*)&S[(r0 + 8) * COUT + cc] = make_float2(acc[nt][2], acc[nt][3]);
        }
    }
    __syncthreads();

    constexpr int CG = COUT / 32;
    for (int task = t; task < 128 * 32; task += 256) {
        int vox  = task >> 5;
        int g    = task & 31;
        int slot = base + vox;
        if (slot >= N) continue;
        float vals[CG], sum = 0.f;
#pragma unroll
        for (int c = 0; c < CG; c++) { vals[c] = S[vox * COUT + g * CG + c]; sum += vals[c]; }
        float mu  = sum * (1.0f / CG);
        float var = 0.f;
#pragma unroll
        for (int c = 0; c < CG; c++) { float d = vals[c] - mu; var += d * d; }
        var *= (1.0f / CG);
        float rs = rsqrtf(var + EPSV);
        if (!FINAL) {
#pragma unroll
            for (int c = 0; c < CG; c++) {
                int cc  = g * CG + c;
                float o = (vals[c] - mu) * rs * gamma[cc] + beta[cc];
                if (LRELU) o = (o > 0.f) ? o : 0.01f * o;
                outc[slot * COUT + cc] = o;
            }
        } else {
            int v = g_list[slot];
#pragma unroll
            for (int c = 0; c < CG; c++) {
                int cc  = g * CG + c;
                float o = (vals[c] - mu) * rs * gamma[cc] + beta[cc]
                        + shortcut[slot * 128 + cc];
                outd[cc * VOX + v] = o;
            }
        }
    }
}

// ---------------- launch ----------------------------------------------------
extern "C" void kernel_launch(void* const* d_in, const int* in_sizes, int n_in,
                              void* d_out, int out_size) {
    (void)in_sizes; (void)n_in; (void)out_size;
    const float* x   = (const float*)d_in[0];
    // d_in[1] = mask (dtype uncertain) — activity derived from x instead.
    const float* W1a = (const float*)d_in[2];
    const float* g1a = (const float*)d_in[3];
    const float* b1a = (const float*)d_in[4];
    const float* W1b = (const float*)d_in[5];
    const float* g1b = (const float*)d_in[6];
    const float* b1b = (const float*)d_in[7];
    const float* W2a = (const float*)d_in[8];
    const float* g2a = (const float*)d_in[9];
    const float* b2a = (const float*)d_in[10];
    const float* W2b = (const float*)d_in[11];
    const float* g2b = (const float*)d_in[12];
    const float* b2b = (const float*)d_in[13];
    float* out = (float*)d_out;

    float *p_xa, *p_s1, *p_r1, *p_sc;
    __nv_bfloat16 *h1a, *l1a, *h1b, *l1b, *h2a, *l2a, *h2b, *l2b;
    cudaGetSymbolAddress((void**)&p_xa, g_xa);
    cudaGetSymbolAddress((void**)&p_s1, g_s1);
    cudaGetSymbolAddress((void**)&p_r1, g_r1);
    cudaGetSymbolAddress((void**)&p_sc, g_sc);
    cudaGetSymbolAddress((void**)&h1a, g_Wh1a); cudaGetSymbolAddress((void**)&l1a, g_Wl1a);
    cudaGetSymbolAddress((void**)&h1b, g_Wh1b); cudaGetSymbolAddress((void**)&l1b, g_Wl1b);
    cudaGetSymbolAddress((void**)&h2a, g_Wh2a); cudaGetSymbolAddress((void**)&l2a, g_Wl2a);
    cudaGetSymbolAddress((void**)&h2b, g_Wh2b); cudaGetSymbolAddress((void**)&l2b, g_Wl2b);

    const int SM64  = 36864 + 2 * 64 * 144;   // 55296 B
    const int SM128 = 36864 + 2 * 128 * 144;  // 73728 B
    cudaFuncSetAttribute(conv_mma<64, 0, true,  false>,
                         cudaFuncAttributeMaxDynamicSharedMemorySize, SM64);
    cudaFuncSetAttribute(conv_mma<64, 2, true,  false>,
                         cudaFuncAttributeMaxDynamicSharedMemorySize, SM64);
    cudaFuncSetAttribute(conv_mma<128, 1, false, false>,
                         cudaFuncAttributeMaxDynamicSharedMemorySize, SM128);
    cudaFuncSetAttribute(conv_mma<128, 0, false, true>,
                         cudaFuncAttributeMaxDynamicSharedMemorySize, SM128);

    cudaMemsetAsync(out, 0, (size_t)VOX * 128 * sizeof(float), 0);

    const int NPREP = 2 * (64 * 64 * 9) + 2 * (128 * 64 * 9);
    prep<<<(NPREP + 255) / 256, 256>>>(W1a, W1b, W2a, W2b);
    pass0<<<VOX / 256, 256>>>(x);

    const int NB = VOX / 128;  // worst-case all-active; blocks early-exit past g_count
    conv_mma<64, 0, true,  false><<<NB, 256, SM64>>>(
        p_xa, h1a, l1a, g1a, b1a, p_s1, nullptr, nullptr);
    conv_mma<64, 2, true,  false><<<NB, 256, SM64>>>(
        p_xa, h2a, l2a, g2a, b2a, p_r1, nullptr, nullptr);
    conv_mma<128, 1, false, false><<<NB, 256, SM128>>>(
        p_s1, h1b, l1b, g1b, b1b, p_sc, nullptr, nullptr);
    conv_mma<128, 0, false, true><<<NB, 256, SM128>>>(
        p_r1, h2b, l2b, g2b, b2b, nullptr, p_sc, out);
}

// round 16
// speedup vs baseline: 2.6806x; 1.0330x over previous
#include <cuda_runtime.h>
#include <cuda_bf16.h>
#include <cstdint>

#define VOX 262144   // 16 * 128 * 128
#define EPSV 1e-5f

// ---------------- scratch (device globals; no allocation allowed) ----------
__device__ int   g_count;
__device__ int   g_map[VOX];
__device__ int   g_list[VOX];
// compact tensors pre-split to bf16 hi/lo  [slot][64]
__device__ __nv_bfloat16 g_xah[VOX * 64], g_xal[VOX * 64];
__device__ __nv_bfloat16 g_s1h[VOX * 64], g_s1l[VOX * 64];
__device__ __nv_bfloat16 g_r1h[VOX * 64], g_r1l[VOX * 64];
__device__ float g_sc[VOX * 128];     // shortcut (fp32) [slot][128]
// weights pre-split to bf16 hi/lo, layout [tap][o][i]  (col operand: n-major, k-contig)
__device__ __nv_bfloat16 g_Wh1a[9*64*64],  g_Wl1a[9*64*64];
__device__ __nv_bfloat16 g_Wh1b[9*128*64], g_Wl1b[9*128*64];
__device__ __nv_bfloat16 g_Wh2a[9*64*64],  g_Wl2a[9*64*64];
__device__ __nv_bfloat16 g_Wh2b[9*128*64], g_Wl2b[9*128*64];

// ---------------- PTX helpers ----------------------------------------------
__device__ __forceinline__ uint32_t sptr(const void* p) {
    return (uint32_t)__cvta_generic_to_shared(p);
}
__device__ __forceinline__ void ldsm_x4(uint32_t* r, uint32_t addr) {
    asm volatile("ldmatrix.sync.aligned.m8n8.x4.shared.b16 {%0,%1,%2,%3}, [%4];"
                 : "=r"(r[0]), "=r"(r[1]), "=r"(r[2]), "=r"(r[3]) : "r"(addr));
}
__device__ __forceinline__ void ldsm_x2(uint32_t* r, uint32_t addr) {
    asm volatile("ldmatrix.sync.aligned.m8n8.x2.shared.b16 {%0,%1}, [%2];"
                 : "=r"(r[0]), "=r"(r[1]) : "r"(addr));
}
__device__ __forceinline__ void mma16816(float* d, const uint32_t* a, const uint32_t* b) {
    asm volatile(
        "mma.sync.aligned.m16n8k16.row.col.f32.bf16.bf16.f32 "
        "{%0,%1,%2,%3}, {%4,%5,%6,%7}, {%8,%9}, {%0,%1,%2,%3};"
        : "+f"(d[0]), "+f"(d[1]), "+f"(d[2]), "+f"(d[3])
        : "r"(a[0]), "r"(a[1]), "r"(a[2]), "r"(a[3]), "r"(b[0]), "r"(b[1]));
}
__device__ __forceinline__ void split_bf16(float f, __nv_bfloat16& h, __nv_bfloat16& l) {
    h = __float2bfloat16(f);
    l = __float2bfloat16(f - __bfloat162float(h));
}

// ---------------- prep: reset counter + split all 4 weights to bf16 hi/lo ---
// W OIDHW flattened: idx = (o*64 + i)*9 + t  ->  Wh/Wl[(t*CO + o)*64 + i]
__device__ __forceinline__ void split_one(const float* __restrict__ W,
                                          __nv_bfloat16* __restrict__ Wh,
                                          __nv_bfloat16* __restrict__ Wl,
                                          int CO, int idx) {
    int t  = idx % 9;
    int oi = idx / 9;
    int i  = oi & 63;
    int o  = oi / 64;
    __nv_bfloat16 hb, lb;
    split_bf16(W[idx], hb, lb);
    Wh[(t * CO + o) * 64 + i] = hb;
    Wl[(t * CO + o) * 64 + i] = lb;
}

__global__ void __launch_bounds__(256) prep(
    const float* __restrict__ W1a, const float* __restrict__ W1b,
    const float* __restrict__ W2a, const float* __restrict__ W2b)
{
    int idx = blockIdx.x * 256 + threadIdx.x;
    if (idx == 0) g_count = 0;
    const int N64 = 64 * 64 * 9, N128 = 128 * 64 * 9;
    if (idx < N64)                 split_one(W1a, g_Wh1a, g_Wl1a, 64,  idx);
    else if ((idx -= N64)  < N128) split_one(W1b, g_Wh1b, g_Wl1b, 128, idx);
    else if ((idx -= N128) < N64)  split_one(W2a, g_Wh2a, g_Wl2a, 64,  idx);
    else if ((idx -= N64)  < N128) split_one(W2b, g_Wh2b, g_Wl2b, 128, idx);
}

// ---------------- pass 0: activity detection + compaction + bf16 split -----
__global__ void __launch_bounds__(256) pass0(const float* __restrict__ x) {
    int v = blockIdx.x * 256 + threadIdx.x;
    float vals[64];
    bool active = false;
#pragma unroll
    for (int c = 0; c < 64; c++) {
        vals[c] = x[c * VOX + v];
        active |= (vals[c] != 0.0f);
    }
    unsigned m   = __ballot_sync(0xffffffffu, active);
    int lane     = threadIdx.x & 31;
    int slot     = -1;
    if (m) {
        int leader = __ffs(m) - 1;
        int base   = 0;
        if (lane == leader) base = atomicAdd(&g_count, __popc(m));
        base = __shfl_sync(0xffffffffu, base, leader);
        if (active) slot = base + __popc(m & ((1u << lane) - 1u));
    }
    g_map[v] = slot;
    if (active) {
        g_list[slot] = v;
#pragma unroll
        for (int c = 0; c < 64; c += 8) {
            uint32_t hw[4], lw[4];
#pragma unroll
            for (int p = 0; p < 4; p++) {
                __nv_bfloat16 h0, l0, h1, l1;
                split_bf16(vals[c + 2*p],     h0, l0);
                split_bf16(vals[c + 2*p + 1], h1, l1);
                hw[p] = (uint32_t)__bfloat16_as_ushort(h0)
                      | ((uint32_t)__bfloat16_as_ushort(h1) << 16);
                lw[p] = (uint32_t)__bfloat16_as_ushort(l0)
                      | ((uint32_t)__bfloat16_as_ushort(l1) << 16);
            }
            *(uint4*)&g_xah[slot * 64 + c] = make_uint4(hw[0], hw[1], hw[2], hw[3]);
            *(uint4*)&g_xal[slot * 64 + c] = make_uint4(lw[0], lw[1], lw[2], lw[3]);
        }
    }
}

// ---------------- warp-MMA gather-GEMM conv + fused GN (+LeakyReLU) --------
// Per block: D[128vox x COUT] = sum_tap X[128x64] @ W_tap[64xCOUT]^T
// Inputs pre-split to bf16 hi/lo -> stage A is pure gather copies (no ALU).
// bf16 2-way split on HMMA (mma.sync m16n8k16), fp32 register accumulators.
// smem rows padded to 144B (9x16B) -> ldmatrix conflict-free, no swizzle.
template <int COUT, int CTYPE, bool LRELU, bool FINAL>
__global__ void __launch_bounds__(256) conv_mma(
    const __nv_bfloat16* __restrict__ inh, const __nv_bfloat16* __restrict__ inl,
    const __nv_bfloat16* __restrict__ Wh, const __nv_bfloat16* __restrict__ Wl,
    const float* __restrict__ gamma, const float* __restrict__ beta,
    __nv_bfloat16* __restrict__ outh, __nv_bfloat16* __restrict__ outl,
    float* __restrict__ outsc,
    const float* __restrict__ shortcut, float* __restrict__ outd)
{
    const int N    = g_count;
    const int base = blockIdx.x * 128;
    if (base >= N) return;

    constexpr int NT  = COUT / 8;        // n-tiles per warp
    constexpr int RS  = 144;             // padded smem row stride (bytes)

    extern __shared__ char smem[];
    __shared__ int nsrow[9 * 128];
    char* Ah = smem;
    char* Al = smem + 18432;
    char* Bh = smem + 36864;
    char* Bl = smem + 36864 + COUT * RS;
    const uint32_t aAH = sptr(Ah), aAL = sptr(Al);
    const uint32_t aBH = sptr(Bh), aBL = sptr(Bl);

    const int t    = threadIdx.x;
    const int w    = t >> 5;
    const int lane = t & 31;
    const int eff  = lane & 15;

    // neighbor slots for all 9 taps
    for (int task = t; task < 9 * 128; task += 256) {
        int tap  = task >> 7;
        int r    = task & 127;
        int slot = base + r, ns = -1;
        if (slot < N) {
            int v = g_list[slot];
            int d = v >> 14, h = (v >> 7) & 127, wd = v & 127;
            int dd, dh, dw;
            if (CTYPE == 0)      { dd = tap / 3 - 1; dh = tap % 3 - 1; dw = 0; }
            else if (CTYPE == 1) { dd = 0;           dh = tap / 3 - 1; dw = tap % 3 - 1; }
            else                 { dd = tap / 3 - 1; dh = 0;           dw = tap % 3 - 1; }
            d += dd; h += dh; wd += dw;
            if ((unsigned)d < 16u && (unsigned)h < 128u && (unsigned)wd < 128u)
                ns = g_map[(d << 14) | (h << 7) | wd];
        }
        nsrow[tap * 128 + r] = ns;
    }
    __syncthreads();

    float acc[NT][4];
#pragma unroll
    for (int nt = 0; nt < NT; nt++)
#pragma unroll
        for (int p = 0; p < 4; p++) acc[nt][p] = 0.f;

    // per-thread ldmatrix base addresses
    const uint32_t aoff  = (uint32_t)(w * 16 + eff) * RS + ((lane >> 4) & 1) * 16;
    const uint32_t boff0 = (uint32_t)(eff & 7) * RS + ((eff >> 3) & 1) * 16;

    const int gr = t >> 1, gh = t & 1;   // A stage: 2 threads per voxel row (64B each)

    for (int tap = 0; tap < 9; tap++) {
        // ---- stage A: pure gather copy of pre-split rows ----
        {
            int ns = nsrow[tap * 128 + gr];
            char* ah = Ah + gr * RS + gh * 64;
            char* al = Al + gr * RS + gh * 64;
            if (ns >= 0) {
                const uint4* sh = (const uint4*)(inh + ns * 64 + gh * 32);
                const uint4* sl = (const uint4*)(inl + ns * 64 + gh * 32);
#pragma unroll
                for (int j = 0; j < 4; j++) {
                    *(uint4*)(ah + j * 16) = sh[j];
                    *(uint4*)(al + j * 16) = sl[j];
                }
            } else {
                uint4 z = make_uint4(0, 0, 0, 0);
#pragma unroll
                for (int j = 0; j < 4; j++) {
                    *(uint4*)(ah + j * 16) = z;
                    *(uint4*)(al + j * 16) = z;
                }
            }
        }
        // ---- stage B: copy pre-split weights into padded rows ----
        {
            const uint4* sh = (const uint4*)(Wh + tap * COUT * 64);
            const uint4* sl = (const uint4*)(Wl + tap * COUT * 64);
#pragma unroll
            for (int u = t; u < COUT * 8; u += 256) {
                int row = u >> 3, part = u & 7;
                *(uint4*)(Bh + row * RS + part * 16) = sh[u];
                *(uint4*)(Bl + row * RS + part * 16) = sl[u];
            }
        }
        __syncthreads();

        // ---- warp-MMA mainloop: 4 k-steps x NT n-tiles x 3 split terms ----
#pragma unroll
        for (int ks = 0; ks < 4; ks++) {
            uint32_t ah[4], al[4];
            ldsm_x4(ah, aAH + aoff + ks * 32);
            ldsm_x4(al, aAL + aoff + ks * 32);
#pragma unroll
            for (int nt = 0; nt < NT; nt++) {
                uint32_t bo = boff0 + (uint32_t)(nt * 8) * RS + ks * 32;
                uint32_t bh[2], bl[2];
                ldsm_x2(bh, aBH + bo);
                ldsm_x2(bl, aBL + bo);
                mma16816(acc[nt], ah, bh);
                mma16816(acc[nt], ah, bl);
                mma16816(acc[nt], al, bh);
            }
        }
        __syncthreads();   // all frags consumed before restaging
    }

    // ---- epilogue: D frags -> smem, then GroupNorm (+LReLU / +shortcut) ----
    float* S = (float*)smem;   // [128][COUT], reuses staging buffers
    {
        int r0 = w * 16 + (lane >> 2);
        int c0 = (lane & 3) * 2;
#pragma unroll
        for (int nt = 0; nt < NT; nt++) {
            int cc = nt * 8 + c0;
            *(float2*)&S[r0 * COUT + cc]       = make_float2(acc[nt][0], acc[nt][1]);
            *(float2*)&S[(r0 + 8) * COUT + cc] = make_float2(acc[nt][2], acc[nt][3]);
        }
    }
    __syncthreads();

    constexpr int CG = COUT / 32;
    for (int task = t; task < 128 * 32; task += 256) {
        int vox  = task >> 5;
        int g    = task & 31;
        int slot = base + vox;
        if (slot >= N) continue;
        float vals[CG], sum = 0.f;
#pragma unroll
        for (int c = 0; c < CG; c++) { vals[c] = S[vox * COUT + g * CG + c]; sum += vals[c]; }
        float mu  = sum * (1.0f / CG);
        float var = 0.f;
#pragma unroll
        for (int c = 0; c < CG; c++) { float d = vals[c] - mu; var += d * d; }
        var *= (1.0f / CG);
        float rs = rsqrtf(var + EPSV);
        if (!FINAL) {
            if (COUT == 64) {
                // split result to bf16 hi/lo for the downstream MMA consumer
#pragma unroll
                for (int c = 0; c < CG; c++) {
                    int cc  = g * CG + c;
                    float o = (vals[c] - mu) * rs * gamma[cc] + beta[cc];
                    if (LRELU) o = (o > 0.f) ? o : 0.01f * o;
                    __nv_bfloat16 hb, lb;
                    split_bf16(o, hb, lb);
                    outh[slot * COUT + cc] = hb;
                    outl[slot * COUT + cc] = lb;
                }
            } else {
                // shortcut producer: keep fp32
#pragma unroll
                for (int c = 0; c < CG; c++) {
                    int cc  = g * CG + c;
                    float o = (vals[c] - mu) * rs * gamma[cc] + beta[cc];
                    if (LRELU) o = (o > 0.f) ? o : 0.01f * o;
                    outsc[slot * COUT + cc] = o;
                }
            }
        } else {
            int v = g_list[slot];
#pragma unroll
            for (int c = 0; c < CG; c++) {
                int cc  = g * CG + c;
                float o = (vals[c] - mu) * rs * gamma[cc] + beta[cc]
                        + shortcut[slot * 128 + cc];
                outd[cc * VOX + v] = o;
            }
        }
    }
}

// ---------------- launch ----------------------------------------------------
extern "C" void kernel_launch(void* const* d_in, const int* in_sizes, int n_in,
                              void* d_out, int out_size) {
    (void)in_sizes; (void)n_in; (void)out_size;
    const float* x   = (const float*)d_in[0];
    // d_in[1] = mask (dtype uncertain) — activity derived from x instead.
    const float* W1a = (const float*)d_in[2];
    const float* g1a = (const float*)d_in[3];
    const float* b1a = (const float*)d_in[4];
    const float* W1b = (const float*)d_in[5];
    const float* g1b = (const float*)d_in[6];
    const float* b1b = (const float*)d_in[7];
    const float* W2a = (const float*)d_in[8];
    const float* g2a = (const float*)d_in[9];
    const float* b2a = (const float*)d_in[10];
    const float* W2b = (const float*)d_in[11];
    const float* g2b = (const float*)d_in[12];
    const float* b2b = (const float*)d_in[13];
    float* out = (float*)d_out;

    float *p_sc;
    __nv_bfloat16 *xah, *xal, *s1h, *s1l, *r1h, *r1l;
    __nv_bfloat16 *h1a, *l1a, *h1b, *l1b, *h2a, *l2a, *h2b, *l2b;
    cudaGetSymbolAddress((void**)&p_sc, g_sc);
    cudaGetSymbolAddress((void**)&xah, g_xah); cudaGetSymbolAddress((void**)&xal, g_xal);
    cudaGetSymbolAddress((void**)&s1h, g_s1h); cudaGetSymbolAddress((void**)&s1l, g_s1l);
    cudaGetSymbolAddress((void**)&r1h, g_r1h); cudaGetSymbolAddress((void**)&r1l, g_r1l);
    cudaGetSymbolAddress((void**)&h1a, g_Wh1a); cudaGetSymbolAddress((void**)&l1a, g_Wl1a);
    cudaGetSymbolAddress((void**)&h1b, g_Wh1b); cudaGetSymbolAddress((void**)&l1b, g_Wl1b);
    cudaGetSymbolAddress((void**)&h2a, g_Wh2a); cudaGetSymbolAddress((void**)&l2a, g_Wl2a);
    cudaGetSymbolAddress((void**)&h2b, g_Wh2b); cudaGetSymbolAddress((void**)&l2b, g_Wl2b);

    const int SM64  = 36864 + 2 * 64 * 144;   // 55296 B
    const int SM128 = 36864 + 2 * 128 * 144;  // 73728 B
    cudaFuncSetAttribute(conv_mma<64, 0, true,  false>,
                         cudaFuncAttributeMaxDynamicSharedMemorySize, SM64);
    cudaFuncSetAttribute(conv_mma<64, 2, true,  false>,
                         cudaFuncAttributeMaxDynamicSharedMemorySize, SM64);
    cudaFuncSetAttribute(conv_mma<128, 1, false, false>,
                         cudaFuncAttributeMaxDynamicSharedMemorySize, SM128);
    cudaFuncSetAttribute(conv_mma<128, 0, false, true>,
                         cudaFuncAttributeMaxDynamicSharedMemorySize, SM128);

    cudaMemsetAsync(out, 0, (size_t)VOX * 128 * sizeof(float), 0);

    const int NPREP = 2 * (64 * 64 * 9) + 2 * (128 * 64 * 9);
    prep<<<(NPREP + 255) / 256, 256>>>(W1a, W1b, W2a, W2b);
    pass0<<<VOX / 256, 256>>>(x);

    const int NB = VOX / 128;  // worst-case all-active; blocks early-exit past g_count
    conv_mma<64, 0, true,  false><<<NB, 256, SM64>>>(
        xah, xal, h1a, l1a, g1a, b1a, s1h, s1l, nullptr, nullptr, nullptr);
    conv_mma<64, 2, true,  false><<<NB, 256, SM64>>>(
        xah, xal, h2a, l2a, g2a, b2a, r1h, r1l, nullptr, nullptr, nullptr);
    conv_mma<128, 1, false, false><<<NB, 256, SM128>>>(
        s1h, s1l, h1b, l1b, g1b, b1b, nullptr, nullptr, p_sc, nullptr, nullptr);
    conv_mma<128, 0, false, true><<<NB, 256, SM128>>>(
        r1h, r1l, h2b, l2b, g2b, b2b, nullptr, nullptr, nullptr, p_sc, out);
}